// round 7
// baseline (speedup 1.0000x reference)
#include <cuda_runtime.h>
#include <cstdint>

#define Nn 32
#define Cc 64
#define Hh 112
#define Wd 112
#define HW (Hh*Wd)            // 12544
#define NHW (Nn*HW)           // 401408
#define TOT (Nn*Cc*HW)        // 25690112
#define BN_EPS 1e-5
#define NCHUNK4 4
#define IMG_PER_CHUNK (Nn/NCHUNK4)          // 8
#define PACK_BLOCKS_TOTAL (NHW/1024)        // 392
#define PACK_BLOCKS_CHUNK (PACK_BLOCKS_TOTAL/NCHUNK4)  // 98

typedef unsigned long long u64;

// ---------------- scratch (device globals) -------------------------------------
__device__ u64       g_xbits[NHW];      // packed input signs (3.2 MB)
__device__ u64       g_wbits[Cc*9];     // packed weight signs
__device__ int       g_rowc[3][Cc];     // row-edge corr: [none,N,S]
__device__ int       g_colw[3][Cc];     // west-col corr given row pattern
__device__ int       g_cole[3][Cc];     // east-col corr given row pattern
__device__ float     g_alpha[Cc];
__device__ long long g_sum[Cc];
__device__ long long g_ss[Cc];
__device__ short     g_conv[TOT];       // NHWC [n][p][c] int16 conv result

// ---------------- K0: pack x signs (round-5 scheme, chunked) + pack W ----------
__global__ __launch_bounds__(256) void pack_k(const float* __restrict__ x,
                                              const float* __restrict__ W,
                                              int chunk) {
    int tid = threadIdx.x;
    int gb  = chunk*PACK_BLOCKS_CHUNK + blockIdx.x;
    if (blockIdx.x < PACK_BLOCKS_CHUNK) {
        int idx = (gb*256 + tid) * 4;               // first pixel id
        int n = idx / HW;
        int p = idx - n*HW;
        const float4* base = (const float4*)(x + (size_t)n*Cc*HW + p);
        unsigned lo0=0, lo1=0, lo2=0, lo3=0, hi0=0, hi1=0, hi2=0, hi3=0;
        #pragma unroll
        for (int c = 0; c < 32; c++) {
            float4 v = base[(size_t)c*(HW/4)];
            lo0 |= (__float_as_uint(v.x) >> 31) << c;
            lo1 |= (__float_as_uint(v.y) >> 31) << c;
            lo2 |= (__float_as_uint(v.z) >> 31) << c;
            lo3 |= (__float_as_uint(v.w) >> 31) << c;
        }
        #pragma unroll
        for (int c = 0; c < 32; c++) {
            float4 v = base[(size_t)(c+32)*(HW/4)];
            hi0 |= (__float_as_uint(v.x) >> 31) << c;
            hi1 |= (__float_as_uint(v.y) >> 31) << c;
            hi2 |= (__float_as_uint(v.z) >> 31) << c;
            hi3 |= (__float_as_uint(v.w) >> 31) << c;
        }
        ulonglong2* dst = (ulonglong2*)&g_xbits[idx];
        dst[0] = make_ulonglong2(((u64)hi0 << 32) | lo0, ((u64)hi1 << 32) | lo1);
        dst[1] = make_ulonglong2(((u64)hi2 << 32) | lo2, ((u64)hi3 << 32) | lo3);
        return;
    }
    // ---- weight packing block (only present in chunk 0's grid) ----
    __shared__ float asum[576];
    __shared__ int   wd_s[Cc][9];
    for (int i = tid; i < 576; i += 256) {
        int co = i / 9, tap = i - co*9;
        u64 bits = 0ull;
        float a = 0.f;
        for (int ci = 0; ci < Cc; ci++) {
            float w = W[(size_t)(co*Cc + ci)*9 + tap];
            a += fabsf(w);
            bits |= ((u64)(__float_as_uint(w) >> 31)) << ci;
        }
        g_wbits[i]    = bits;
        wd_s[co][tap] = 64 - 2*__popcll(bits);
        asum[i]       = a;
    }
    if (tid < Cc) { g_sum[tid] = 0; g_ss[tid] = 0; }
    __syncthreads();
    if (tid < Cc) {
        int co = tid;
        float t = 0.f;
        #pragma unroll
        for (int k = 0; k < 9; k++) t += asum[co*9 + k];
        g_alpha[co] = t / 576.f;
        int w0=wd_s[co][0], w1=wd_s[co][1], w2=wd_s[co][2];
        int w3=wd_s[co][3],               w5=wd_s[co][5];
        int w6=wd_s[co][6], w7=wd_s[co][7], w8=wd_s[co][8];
        g_rowc[0][co] = 0;
        g_rowc[1][co] = w0 + w1 + w2;
        g_rowc[2][co] = w6 + w7 + w8;
        g_colw[0][co] = w0 + w3 + w6;
        g_colw[1][co] = w3 + w6;
        g_colw[2][co] = w0 + w3;
        g_cole[0][co] = w2 + w5 + w8;
        g_cole[1][co] = w5 + w8;
        g_cole[2][co] = w2 + w5;
    }
}

// ---------------- K1: sliding-window popcount conv + fused exact BN stats ------
__global__ __launch_bounds__(256, 2) void conv_k(int chunk) {
    __shared__ u64 xs[18*18];
    __shared__ int sRow[3][Cc], sW[3][Cc], sE[3][Cc];
    __shared__ int st[4][8][32];

    int tid  = threadIdx.x;
    int pair = tid & 31;
    int grp  = tid >> 5;
    int n  = chunk*IMG_PER_CHUNK + blockIdx.z;
    int h0 = blockIdx.y * 16, w0 = blockIdx.x * 16;

    for (int j = tid; j < 18*18; j += 256) {
        int lh = j / 18, lw = j - lh*18;
        int gh = h0 + lh - 1, gw = w0 + lw - 1;
        u64 v = 0ull;
        if (gh >= 0 && gh < Hh && gw >= 0 && gw < Wd)
            v = g_xbits[(size_t)n*HW + gh*Wd + gw];
        xs[j] = v;
    }
    if (tid < 192) {
        int r = tid >> 6, c = tid & 63;
        sRow[r][c] = g_rowc[r][c];
        sW[r][c]   = g_colw[r][c];
        sE[r][c]   = g_cole[r][c];
    }

    int c0 = pair*2;
    u64 wb0[9], wb1[9];
    #pragma unroll
    for (int t = 0; t < 9; t++) {
        wb0[t] = g_wbits[c0*9 + t];
        wb1[t] = g_wbits[(c0+1)*9 + t];
    }
    __syncthreads();

    const bool wleft  = (w0 == 0);
    const bool wright = (w0 == Wd-16);
    int as0 = 0, ass0 = 0, as1 = 0, ass1 = 0;

    #pragma unroll
    for (int r = 0; r < 2; r++) {
        int ohl = grp*2 + r;
        int oh  = h0 + ohl;
        int rp  = (oh == 0) ? 1 : ((oh == Hh-1) ? 2 : 0);
        int base0 = 576 - sRow[rp][c0];
        int base1 = 576 - sRow[rp][c0+1];
        int cw0 = sW[rp][c0], cw1 = sW[rp][c0+1];
        int ce0 = sE[rp][c0], ce1 = sE[rp][c0+1];

        const u64* r0p = &xs[ohl*18];
        const u64* r1p = r0p + 18;
        const u64* r2p = r1p + 18;
        u64 x00 = r0p[0], x01 = r0p[1];
        u64 x10 = r1p[0], x11 = r1p[1];
        u64 x20 = r2p[0], x21 = r2p[1];

        unsigned* op = ((unsigned*)g_conv) + ((size_t)n*HW + (size_t)oh*Wd + w0)*32 + pair;

        #pragma unroll
        for (int w = 0; w < 16; w++) {
            u64 x02 = r0p[w+2], x12 = r1p[w+2], x22 = r2p[w+2];
            int pc0 = __popcll(x00^wb0[0]) + __popcll(x01^wb0[1]) + __popcll(x02^wb0[2])
                    + __popcll(x10^wb0[3]) + __popcll(x11^wb0[4]) + __popcll(x12^wb0[5])
                    + __popcll(x20^wb0[6]) + __popcll(x21^wb0[7]) + __popcll(x22^wb0[8]);
            int pc1 = __popcll(x00^wb1[0]) + __popcll(x01^wb1[1]) + __popcll(x02^wb1[2])
                    + __popcll(x10^wb1[3]) + __popcll(x11^wb1[4]) + __popcll(x12^wb1[5])
                    + __popcll(x20^wb1[6]) + __popcll(x21^wb1[7]) + __popcll(x22^wb1[8]);
            int s0 = base0 - 2*pc0;
            int s1 = base1 - 2*pc1;
            if (w == 0  && wleft)  { s0 -= cw0; s1 -= cw1; }
            if (w == 15 && wright) { s0 -= ce0; s1 -= ce1; }

            as0 += s0; ass0 += s0*s0;
            as1 += s1; ass1 += s1*s1;
            *op = ((unsigned)s0 & 0xFFFFu) | ((unsigned)s1 << 16);
            op += 32;

            x00 = x01; x01 = x02;
            x10 = x11; x11 = x12;
            x20 = x21; x21 = x22;
        }
    }

    st[0][grp][pair] = as0; st[1][grp][pair] = ass0;
    st[2][grp][pair] = as1; st[3][grp][pair] = ass1;
    __syncthreads();
    if (grp == 0) {
        int bs0=0, bss0=0, bs1=0, bss1=0;
        #pragma unroll
        for (int g = 0; g < 8; g++) {
            bs0 += st[0][g][pair]; bss0 += st[1][g][pair];
            bs1 += st[2][g][pair]; bss1 += st[3][g][pair];
        }
        atomicAdd((unsigned long long*)&g_sum[c0],   (unsigned long long)(long long)bs0);
        atomicAdd((unsigned long long*)&g_ss[c0],    (unsigned long long)(long long)bss0);
        atomicAdd((unsigned long long*)&g_sum[c0+1], (unsigned long long)(long long)bs1);
        atomicAdd((unsigned long long*)&g_ss[c0+1],  (unsigned long long)(long long)bss1);
    }
}

// ---------------- K2: per-block affine fold + hardtanh + residual --------------
__global__ __launch_bounds__(256) void apply_k(const float* __restrict__ x,
                                               const float* __restrict__ gamma,
                                               const float* __restrict__ beta,
                                               float* __restrict__ out) {
    __shared__ float sA[Cc], sB[Cc];
    int tid = threadIdx.x;
    if (tid < Cc) {
        int c = tid;
        double mean = (double)g_sum[c] / (double)NHW;
        double ex2  = (double)g_ss[c]  / (double)NHW;
        double a    = (double)g_alpha[c];
        double var  = a*a*(ex2 - mean*mean);
        double rs   = 1.0 / sqrt(var + BN_EPS);
        double g    = (double)gamma[c];
        sA[c] = (float)(a * rs * g);
        sB[c] = (float)((double)beta[c] - a * mean * rs * g);
    }
    __syncthreads();

    size_t P = (size_t)blockIdx.x*256 + tid;      // global pixel id
    int n = (int)(P / HW);
    int p = (int)(P - (size_t)n*HW);
    const uint4* cb = (const uint4*)g_conv + P*8;           // 128B of NHWC shorts
    const float* xb = x   + (size_t)n*Cc*HW + p;
    float*       ob = out + (size_t)n*Cc*HW + p;

    #pragma unroll
    for (int q = 0; q < 8; q++) {
        uint4 v = cb[q];
        #pragma unroll
        for (int w = 0; w < 4; w++) {
            uint32_t u = (&v.x)[w];
            int cA = (q*4 + w)*2;
            int sv0 = (int)((int32_t)(u << 16) >> 16);
            int sv1 = (int)((int32_t)u >> 16);
            float r0 = fminf(fmaxf(fmaf((float)sv0, sA[cA],   sB[cA]),   -1.f), 1.f);
            float r1 = fminf(fmaxf(fmaf((float)sv1, sA[cA+1], sB[cA+1]), -1.f), 1.f);
            ob[(size_t)cA*HW]     = r0 + xb[(size_t)cA*HW];
            ob[(size_t)(cA+1)*HW] = r1 + xb[(size_t)(cA+1)*HW];
        }
    }
}

// ---------------- launcher: pipelined pack/conv on 2 streams -------------------
static cudaStream_t g_s1 = nullptr;
static cudaEvent_t  g_evFork = nullptr, g_ev[3] = {nullptr, nullptr, nullptr};

extern "C" void kernel_launch(void* const* d_in, const int* in_sizes, int n_in,
                              void* d_out, int out_size) {
    const float* x     = (const float*)d_in[0];
    const float* W     = (const float*)d_in[1];
    const float* gamma = (const float*)d_in[2];
    const float* beta  = (const float*)d_in[3];
    float* out = (float*)d_out;

    if (!g_s1) {   // one-time setup on the (non-captured) correctness call
        cudaStreamCreateWithFlags(&g_s1, cudaStreamNonBlocking);
        cudaEventCreateWithFlags(&g_evFork, cudaEventDisableTiming);
        for (int i = 0; i < 3; i++)
            cudaEventCreateWithFlags(&g_ev[i], cudaEventDisableTiming);
    }

    // chunk 0 pack (+ weight pack) on the main stream
    pack_k<<<PACK_BLOCKS_CHUNK + 1, 256>>>(x, W, 0);
    cudaEventRecord(g_evFork, 0);
    cudaStreamWaitEvent(g_s1, g_evFork, 0);

    // chunks 1..3 pack on side stream, overlapping conv below
    for (int c = 1; c < NCHUNK4; c++) {
        pack_k<<<PACK_BLOCKS_CHUNK, 256, 0, g_s1>>>(x, W, c);
        cudaEventRecord(g_ev[c-1], g_s1);
    }

    // convs on main stream; conv(c) waits pack(c)
    conv_k<<<dim3(7, 7, IMG_PER_CHUNK), 256>>>(0);
    for (int c = 1; c < NCHUNK4; c++) {
        cudaStreamWaitEvent(0, g_ev[c-1], 0);
        conv_k<<<dim3(7, 7, IMG_PER_CHUNK), 256>>>(c);
    }

    // epilogue (needs global BN stats -> after all convs)
    apply_k<<<NHW/256, 256>>>(x, gamma, beta, out);
}

// round 8
// speedup vs baseline: 1.0964x; 1.0964x over previous
#include <cuda_runtime.h>
#include <cstdint>

#define Nn 32
#define Cc 64
#define Hh 112
#define Wd 112
#define HW (Hh*Wd)            // 12544
#define NHW (Nn*HW)           // 401408
#define TOT (Nn*Cc*HW)        // 25690112
#define BN_EPS 1e-5
#define PACK_HALF_BLOCKS (NHW/1024)      // 392 blocks per channel-half
#define PACK_BLOCKS (2*PACK_HALF_BLOCKS) // 784

typedef unsigned long long u64;

// ---------------- scratch (device globals) -------------------------------------
__device__ unsigned  g_xlo[NHW];        // packed signs, channels 0-31
__device__ unsigned  g_xhi[NHW];        // packed signs, channels 32-63
__device__ u64       g_wbits[Cc*9];     // packed weight signs
__device__ int       g_rowc[3][Cc];     // row-edge corr: [none,N,S]
__device__ int       g_colw[3][Cc];     // west-col corr given row pattern
__device__ int       g_cole[3][Cc];     // east-col corr given row pattern
__device__ float     g_alpha[Cc];
__device__ long long g_sum[Cc];
__device__ long long g_ss[Cc];
__device__ short     g_conv[TOT];       // NHWC [n][p][c] int16 conv result

// ---------------- K0: pack x signs (split lo/hi planes) + pack W ---------------
__global__ __launch_bounds__(256) void pack_k(const float* __restrict__ x,
                                              const float* __restrict__ W) {
    int tid = threadIdx.x;
    if (blockIdx.x < PACK_BLOCKS) {
        int half = (blockIdx.x >= PACK_HALF_BLOCKS) ? 1 : 0;
        int b    = blockIdx.x - half*PACK_HALF_BLOCKS;
        int idx  = (b*256 + tid) * 4;               // first pixel id
        int n = idx / HW;
        int p = idx - n*HW;
        const float4* base =
            (const float4*)(x + (size_t)n*Cc*HW + (size_t)half*32*HW + p);
        unsigned w0=0, w1=0, w2=0, w3=0;
        #pragma unroll
        for (int c = 0; c < 32; c++) {
            float4 v = base[(size_t)c*(HW/4)];
            w0 |= (__float_as_uint(v.x) >> 31) << c;
            w1 |= (__float_as_uint(v.y) >> 31) << c;
            w2 |= (__float_as_uint(v.z) >> 31) << c;
            w3 |= (__float_as_uint(v.w) >> 31) << c;
        }
        uint4 st = make_uint4(w0, w1, w2, w3);
        if (half == 0) ((uint4*)g_xlo)[idx >> 2] = st;
        else           ((uint4*)g_xhi)[idx >> 2] = st;
        return;
    }
    // ---- weight packing block ----
    __shared__ float asum[576];
    __shared__ int   wd_s[Cc][9];
    for (int i = tid; i < 576; i += 256) {
        int co = i / 9, tap = i - co*9;
        u64 bits = 0ull;
        float a = 0.f;
        for (int ci = 0; ci < Cc; ci++) {
            float w = W[(size_t)(co*Cc + ci)*9 + tap];
            a += fabsf(w);
            bits |= ((u64)(__float_as_uint(w) >> 31)) << ci;
        }
        g_wbits[i]    = bits;
        wd_s[co][tap] = 64 - 2*__popcll(bits);
        asum[i]       = a;
    }
    if (tid < Cc) { g_sum[tid] = 0; g_ss[tid] = 0; }
    __syncthreads();
    if (tid < Cc) {
        int co = tid;
        float t = 0.f;
        #pragma unroll
        for (int k = 0; k < 9; k++) t += asum[co*9 + k];
        g_alpha[co] = t / 576.f;
        int w0=wd_s[co][0], w1=wd_s[co][1], w2=wd_s[co][2];
        int w3=wd_s[co][3],               w5=wd_s[co][5];
        int w6=wd_s[co][6], w7=wd_s[co][7], w8=wd_s[co][8];
        g_rowc[0][co] = 0;
        g_rowc[1][co] = w0 + w1 + w2;
        g_rowc[2][co] = w6 + w7 + w8;
        g_colw[0][co] = w0 + w3 + w6;
        g_colw[1][co] = w3 + w6;
        g_colw[2][co] = w0 + w3;
        g_cole[0][co] = w2 + w5 + w8;
        g_cole[1][co] = w5 + w8;
        g_cole[2][co] = w2 + w5;
    }
}

// ---------------- K1: sliding-window popcount conv + fused exact BN stats ------
__global__ __launch_bounds__(256, 2) void conv_k() {
    __shared__ u64 xs[18*18];
    __shared__ int sRow[3][Cc], sW[3][Cc], sE[3][Cc];
    __shared__ int st[4][8][32];

    int tid  = threadIdx.x;
    int pair = tid & 31;
    int grp  = tid >> 5;
    int n  = blockIdx.z;
    int h0 = blockIdx.y * 16, w0 = blockIdx.x * 16;

    for (int j = tid; j < 18*18; j += 256) {
        int lh = j / 18, lw = j - lh*18;
        int gh = h0 + lh - 1, gw = w0 + lw - 1;
        u64 v = 0ull;
        if (gh >= 0 && gh < Hh && gw >= 0 && gw < Wd) {
            size_t off = (size_t)n*HW + gh*Wd + gw;
            v = ((u64)g_xhi[off] << 32) | (u64)g_xlo[off];
        }
        xs[j] = v;
    }
    if (tid < 192) {
        int r = tid >> 6, c = tid & 63;
        sRow[r][c] = g_rowc[r][c];
        sW[r][c]   = g_colw[r][c];
        sE[r][c]   = g_cole[r][c];
    }

    int c0 = pair*2;
    u64 wb0[9], wb1[9];
    #pragma unroll
    for (int t = 0; t < 9; t++) {
        wb0[t] = g_wbits[c0*9 + t];
        wb1[t] = g_wbits[(c0+1)*9 + t];
    }
    __syncthreads();

    const bool wleft  = (w0 == 0);
    const bool wright = (w0 == Wd-16);
    int as0 = 0, ass0 = 0, as1 = 0, ass1 = 0;

    #pragma unroll
    for (int r = 0; r < 2; r++) {
        int ohl = grp*2 + r;
        int oh  = h0 + ohl;
        int rp  = (oh == 0) ? 1 : ((oh == Hh-1) ? 2 : 0);
        int base0 = 576 - sRow[rp][c0];
        int base1 = 576 - sRow[rp][c0+1];
        int cw0 = sW[rp][c0], cw1 = sW[rp][c0+1];
        int ce0 = sE[rp][c0], ce1 = sE[rp][c0+1];

        const u64* r0p = &xs[ohl*18];
        const u64* r1p = r0p + 18;
        const u64* r2p = r1p + 18;
        u64 x00 = r0p[0], x01 = r0p[1];
        u64 x10 = r1p[0], x11 = r1p[1];
        u64 x20 = r2p[0], x21 = r2p[1];

        unsigned* op = ((unsigned*)g_conv) + ((size_t)n*HW + (size_t)oh*Wd + w0)*32 + pair;

        #pragma unroll
        for (int w = 0; w < 16; w++) {
            u64 x02 = r0p[w+2], x12 = r1p[w+2], x22 = r2p[w+2];
            int pc0 = __popcll(x00^wb0[0]) + __popcll(x01^wb0[1]) + __popcll(x02^wb0[2])
                    + __popcll(x10^wb0[3]) + __popcll(x11^wb0[4]) + __popcll(x12^wb0[5])
                    + __popcll(x20^wb0[6]) + __popcll(x21^wb0[7]) + __popcll(x22^wb0[8]);
            int pc1 = __popcll(x00^wb1[0]) + __popcll(x01^wb1[1]) + __popcll(x02^wb1[2])
                    + __popcll(x10^wb1[3]) + __popcll(x11^wb1[4]) + __popcll(x12^wb1[5])
                    + __popcll(x20^wb1[6]) + __popcll(x21^wb1[7]) + __popcll(x22^wb1[8]);
            int s0 = base0 - 2*pc0;
            int s1 = base1 - 2*pc1;
            if (w == 0  && wleft)  { s0 -= cw0; s1 -= cw1; }
            if (w == 15 && wright) { s0 -= ce0; s1 -= ce1; }

            as0 += s0; ass0 += s0*s0;
            as1 += s1; ass1 += s1*s1;
            *op = ((unsigned)s0 & 0xFFFFu) | ((unsigned)s1 << 16);
            op += 32;

            x00 = x01; x01 = x02;
            x10 = x11; x11 = x12;
            x20 = x21; x21 = x22;
        }
    }

    st[0][grp][pair] = as0; st[1][grp][pair] = ass0;
    st[2][grp][pair] = as1; st[3][grp][pair] = ass1;
    __syncthreads();
    if (grp == 0) {
        int bs0=0, bss0=0, bs1=0, bss1=0;
        #pragma unroll
        for (int g = 0; g < 8; g++) {
            bs0 += st[0][g][pair]; bss0 += st[1][g][pair];
            bs1 += st[2][g][pair]; bss1 += st[3][g][pair];
        }
        atomicAdd((unsigned long long*)&g_sum[c0],   (unsigned long long)(long long)bs0);
        atomicAdd((unsigned long long*)&g_ss[c0],    (unsigned long long)(long long)bss0);
        atomicAdd((unsigned long long*)&g_sum[c0+1], (unsigned long long)(long long)bs1);
        atomicAdd((unsigned long long*)&g_ss[c0+1],  (unsigned long long)(long long)bss1);
    }
}

// ---------------- K2: per-block affine fold + hardtanh + residual --------------
__global__ __launch_bounds__(256) void apply_k(const float* __restrict__ x,
                                               const float* __restrict__ gamma,
                                               const float* __restrict__ beta,
                                               float* __restrict__ out) {
    __shared__ float sA[Cc], sB[Cc];
    int tid = threadIdx.x;
    if (tid < Cc) {
        int c = tid;
        double mean = (double)g_sum[c] / (double)NHW;
        double ex2  = (double)g_ss[c]  / (double)NHW;
        double a    = (double)g_alpha[c];
        double var  = a*a*(ex2 - mean*mean);
        double rs   = 1.0 / sqrt(var + BN_EPS);
        double g    = (double)gamma[c];
        sA[c] = (float)(a * rs * g);
        sB[c] = (float)((double)beta[c] - a * mean * rs * g);
    }
    __syncthreads();

    size_t P = (size_t)blockIdx.x*256 + tid;      // global pixel id
    int n = (int)(P / HW);
    int p = (int)(P - (size_t)n*HW);
    const uint4* cb = (const uint4*)g_conv + P*8;           // 128B of NHWC shorts
    const float* xb = x   + (size_t)n*Cc*HW + p;
    float*       ob = out + (size_t)n*Cc*HW + p;

    #pragma unroll
    for (int q = 0; q < 8; q++) {
        uint4 v = cb[q];
        #pragma unroll
        for (int w = 0; w < 4; w++) {
            uint32_t u = (&v.x)[w];
            int cA = (q*4 + w)*2;
            int sv0 = (int)((int32_t)(u << 16) >> 16);
            int sv1 = (int)((int32_t)u >> 16);
            float r0 = fminf(fmaxf(fmaf((float)sv0, sA[cA],   sB[cA]),   -1.f), 1.f);
            float r1 = fminf(fmaxf(fmaf((float)sv1, sA[cA+1], sB[cA+1]), -1.f), 1.f);
            ob[(size_t)cA*HW]     = r0 + xb[(size_t)cA*HW];
            ob[(size_t)(cA+1)*HW] = r1 + xb[(size_t)(cA+1)*HW];
        }
    }
}

// ---------------- launcher ------------------------------------------------------
extern "C" void kernel_launch(void* const* d_in, const int* in_sizes, int n_in,
                              void* d_out, int out_size) {
    const float* x     = (const float*)d_in[0];
    const float* W     = (const float*)d_in[1];
    const float* gamma = (const float*)d_in[2];
    const float* beta  = (const float*)d_in[3];
    float* out = (float*)d_out;

    pack_k<<<PACK_BLOCKS + 1, 256>>>(x, W);
    conv_k<<<dim3(7, 7, Nn), 256>>>();
    apply_k<<<NHW/256, 256>>>(x, gamma, beta, out);
}

// round 9
// speedup vs baseline: 1.1873x; 1.0829x over previous
#include <cuda_runtime.h>
#include <cstdint>

#define Nn 32
#define Cc 64
#define Hh 112
#define Wd 112
#define HW (Hh*Wd)            // 12544
#define NHW (Nn*HW)           // 401408
#define TOT (Nn*Cc*HW)        // 25690112
#define BN_EPS 1e-5

typedef unsigned long long u64;

// ---------------- scratch (device globals) -------------------------------------
__device__ u64       g_wbits[Cc*9];     // packed weight signs
__device__ int       g_rowc[3][Cc];     // row-edge corr: [none,N,S]
__device__ int       g_colw[3][Cc];     // west-col corr given row pattern
__device__ int       g_cole[3][Cc];     // east-col corr given row pattern
__device__ float     g_alpha[Cc];
__device__ long long g_sum[Cc];
__device__ long long g_ss[Cc];
__device__ short     g_conv[TOT];       // NHWC [n][p][c] int16 conv result

// ---------------- K0: pack W + alpha + border-correction tables ----------------
__global__ void packW_k(const float* __restrict__ W) {
    __shared__ float asum[576];
    __shared__ int   wd_s[Cc][9];
    int i = threadIdx.x;                 // 0..575 = (co, tap)
    int co = i / 9, tap = i - co*9;
    u64 bits = 0ull;
    float a = 0.f;
    for (int ci = 0; ci < Cc; ci++) {
        float w = W[(size_t)(co*Cc + ci)*9 + tap];
        a += fabsf(w);
        bits |= ((u64)(__float_as_uint(w) >> 31)) << ci;
    }
    g_wbits[i]    = bits;
    wd_s[co][tap] = 64 - 2*__popcll(bits);
    asum[i]       = a;
    if (i < Cc) { g_sum[i] = 0; g_ss[i] = 0; }
    __syncthreads();
    if (i < Cc) {
        int c = i;
        float t = 0.f;
        #pragma unroll
        for (int k = 0; k < 9; k++) t += asum[c*9 + k];
        g_alpha[c] = t / 576.f;
        int w0=wd_s[c][0], w1=wd_s[c][1], w2=wd_s[c][2];
        int w3=wd_s[c][3],              w5=wd_s[c][5];
        int w6=wd_s[c][6], w7=wd_s[c][7], w8=wd_s[c][8];
        g_rowc[0][c] = 0;
        g_rowc[1][c] = w0 + w1 + w2;
        g_rowc[2][c] = w6 + w7 + w8;
        g_colw[0][c] = w0 + w3 + w6;
        g_colw[1][c] = w3 + w6;
        g_colw[2][c] = w0 + w3;
        g_cole[0][c] = w2 + w5 + w8;
        g_cole[1][c] = w5 + w8;
        g_cole[2][c] = w2 + w5;
    }
}

// ---------------- K1: fused pack + sliding-window popcount conv + BN stats -----
// 16x16 pixel tile per block. Halo stage packs 64-channel signs straight from x.
__global__ __launch_bounds__(256, 2) void conv_k(const float* __restrict__ x) {
    __shared__ u64 xs[18*18];
    __shared__ int sRow[3][Cc], sW[3][Cc], sE[3][Cc];
    __shared__ int st[4][8][32];

    int tid  = threadIdx.x;
    int pair = tid & 31;
    int grp  = tid >> 5;
    int n  = blockIdx.z;
    int h0 = blockIdx.y * 16, w0 = blockIdx.x * 16;

    // fused halo pack: read 64 channel floats per halo pixel, pack sign bits
    const float* xn = x + (size_t)n*Cc*HW;
    for (int j = tid; j < 18*18; j += 256) {
        int lh = j / 18, lw = j - lh*18;
        int gh = h0 + lh - 1, gw = w0 + lw - 1;
        u64 v = 0ull;
        if (gh >= 0 && gh < Hh && gw >= 0 && gw < Wd) {
            const float* px = xn + gh*Wd + gw;
            unsigned lo = 0, hi = 0;
            #pragma unroll
            for (int c = 0; c < 32; c++)
                lo |= (__float_as_uint(__ldg(px + (size_t)c*HW)) >> 31) << c;
            #pragma unroll
            for (int c = 0; c < 32; c++)
                hi |= (__float_as_uint(__ldg(px + (size_t)(c+32)*HW)) >> 31) << c;
            v = ((u64)hi << 32) | lo;
        }
        xs[j] = v;
    }
    if (tid < 192) {
        int r = tid >> 6, c = tid & 63;
        sRow[r][c] = g_rowc[r][c];
        sW[r][c]   = g_colw[r][c];
        sE[r][c]   = g_cole[r][c];
    }

    int c0 = pair*2;
    u64 wb0[9], wb1[9];
    #pragma unroll
    for (int t = 0; t < 9; t++) {
        wb0[t] = g_wbits[c0*9 + t];
        wb1[t] = g_wbits[(c0+1)*9 + t];
    }
    __syncthreads();

    const bool wleft  = (w0 == 0);
    const bool wright = (w0 == Wd-16);
    int as0 = 0, ass0 = 0, as1 = 0, ass1 = 0;

    #pragma unroll
    for (int r = 0; r < 2; r++) {
        int ohl = grp*2 + r;
        int oh  = h0 + ohl;
        int rp  = (oh == 0) ? 1 : ((oh == Hh-1) ? 2 : 0);
        int base0 = 576 - sRow[rp][c0];
        int base1 = 576 - sRow[rp][c0+1];
        int cw0 = sW[rp][c0], cw1 = sW[rp][c0+1];
        int ce0 = sE[rp][c0], ce1 = sE[rp][c0+1];

        const u64* r0p = &xs[ohl*18];
        const u64* r1p = r0p + 18;
        const u64* r2p = r1p + 18;
        u64 x00 = r0p[0], x01 = r0p[1];
        u64 x10 = r1p[0], x11 = r1p[1];
        u64 x20 = r2p[0], x21 = r2p[1];

        unsigned* op = ((unsigned*)g_conv) + ((size_t)n*HW + (size_t)oh*Wd + w0)*32 + pair;

        #pragma unroll
        for (int w = 0; w < 16; w++) {
            u64 x02 = r0p[w+2], x12 = r1p[w+2], x22 = r2p[w+2];
            int pc0 = __popcll(x00^wb0[0]) + __popcll(x01^wb0[1]) + __popcll(x02^wb0[2])
                    + __popcll(x10^wb0[3]) + __popcll(x11^wb0[4]) + __popcll(x12^wb0[5])
                    + __popcll(x20^wb0[6]) + __popcll(x21^wb0[7]) + __popcll(x22^wb0[8]);
            int pc1 = __popcll(x00^wb1[0]) + __popcll(x01^wb1[1]) + __popcll(x02^wb1[2])
                    + __popcll(x10^wb1[3]) + __popcll(x11^wb1[4]) + __popcll(x12^wb1[5])
                    + __popcll(x20^wb1[6]) + __popcll(x21^wb1[7]) + __popcll(x22^wb1[8]);
            int s0 = base0 - 2*pc0;
            int s1 = base1 - 2*pc1;
            if (w == 0  && wleft)  { s0 -= cw0; s1 -= cw1; }
            if (w == 15 && wright) { s0 -= ce0; s1 -= ce1; }

            as0 += s0; ass0 += s0*s0;
            as1 += s1; ass1 += s1*s1;
            *op = ((unsigned)s0 & 0xFFFFu) | ((unsigned)s1 << 16);
            op += 32;

            x00 = x01; x01 = x02;
            x10 = x11; x11 = x12;
            x20 = x21; x21 = x22;
        }
    }

    st[0][grp][pair] = as0; st[1][grp][pair] = ass0;
    st[2][grp][pair] = as1; st[3][grp][pair] = ass1;
    __syncthreads();
    if (grp == 0) {
        int bs0=0, bss0=0, bs1=0, bss1=0;
        #pragma unroll
        for (int g = 0; g < 8; g++) {
            bs0 += st[0][g][pair]; bss0 += st[1][g][pair];
            bs1 += st[2][g][pair]; bss1 += st[3][g][pair];
        }
        atomicAdd((unsigned long long*)&g_sum[c0],   (unsigned long long)(long long)bs0);
        atomicAdd((unsigned long long*)&g_ss[c0],    (unsigned long long)(long long)bss0);
        atomicAdd((unsigned long long*)&g_sum[c0+1], (unsigned long long)(long long)bs1);
        atomicAdd((unsigned long long*)&g_ss[c0+1],  (unsigned long long)(long long)bss1);
    }
}

// ---------------- K2: per-block affine fold + hardtanh + residual --------------
__global__ __launch_bounds__(256) void apply_k(const float* __restrict__ x,
                                               const float* __restrict__ gamma,
                                               const float* __restrict__ beta,
                                               float* __restrict__ out) {
    __shared__ float sA[Cc], sB[Cc];
    int tid = threadIdx.x;
    if (tid < Cc) {
        int c = tid;
        double mean = (double)g_sum[c] / (double)NHW;
        double ex2  = (double)g_ss[c]  / (double)NHW;
        double a    = (double)g_alpha[c];
        double var  = a*a*(ex2 - mean*mean);
        double rs   = 1.0 / sqrt(var + BN_EPS);
        double g    = (double)gamma[c];
        sA[c] = (float)(a * rs * g);
        sB[c] = (float)((double)beta[c] - a * mean * rs * g);
    }
    __syncthreads();

    size_t P = (size_t)blockIdx.x*256 + tid;      // global pixel id
    int n = (int)(P / HW);
    int p = (int)(P - (size_t)n*HW);
    const uint4* cb = (const uint4*)g_conv + P*8;           // 128B of NHWC shorts
    const float* xb = x   + (size_t)n*Cc*HW + p;
    float*       ob = out + (size_t)n*Cc*HW + p;

    #pragma unroll
    for (int q = 0; q < 8; q++) {
        uint4 v = cb[q];
        #pragma unroll
        for (int w = 0; w < 4; w++) {
            uint32_t u = (&v.x)[w];
            int cA = (q*4 + w)*2;
            int sv0 = (int)((int32_t)(u << 16) >> 16);
            int sv1 = (int)((int32_t)u >> 16);
            float r0 = fminf(fmaxf(fmaf((float)sv0, sA[cA],   sB[cA]),   -1.f), 1.f);
            float r1 = fminf(fmaxf(fmaf((float)sv1, sA[cA+1], sB[cA+1]), -1.f), 1.f);
            ob[(size_t)cA*HW]     = r0 + xb[(size_t)cA*HW];
            ob[(size_t)(cA+1)*HW] = r1 + xb[(size_t)(cA+1)*HW];
        }
    }
}

// ---------------- launcher ------------------------------------------------------
extern "C" void kernel_launch(void* const* d_in, const int* in_sizes, int n_in,
                              void* d_out, int out_size) {
    const float* x     = (const float*)d_in[0];
    const float* W     = (const float*)d_in[1];
    const float* gamma = (const float*)d_in[2];
    const float* beta  = (const float*)d_in[3];
    float* out = (float*)d_out;

    packW_k<<<1, 576>>>(W);
    conv_k<<<dim3(7, 7, Nn), 256>>>(x);
    apply_k<<<NHW/256, 256>>>(x, gamma, beta, out);
}

// round 10
// speedup vs baseline: 1.1880x; 1.0006x over previous
#include <cuda_runtime.h>
#include <cstdint>

#define Nn 32
#define Cc 64
#define Hh 112
#define Wd 112
#define HW (Hh*Wd)            // 12544
#define NHW (Nn*HW)           // 401408
#define TOT (Nn*Cc*HW)        // 25690112
#define BN_EPS 1e-5

typedef unsigned long long u64;

// ---------------- scratch (device globals) -------------------------------------
__device__ u64       g_wbits[Cc*9];     // packed weight signs
__device__ float     g_wasum[Cc*9*2];   // per-(co,tap,half) partial |w| sums
__device__ long long g_sum[Cc];
__device__ long long g_ss[Cc];
__device__ short     g_conv[TOT];       // NHWC [n][p][c] int16 conv result

// ---------------- K0: pack W via ballot (144 blocks, 1 warp per (co,tap,half)) -
__global__ __launch_bounds__(256) void packW_k(const float* __restrict__ W) {
    int gw   = blockIdx.x*8 + (threadIdx.x >> 5);   // 0..1151
    int lane = threadIdx.x & 31;
    int co   = gw / 18;
    int rem  = gw - co*18;
    int tap  = rem >> 1;
    int half = rem & 1;
    float w = W[(size_t)(co*Cc + half*32 + lane)*9 + tap];
    unsigned bits = __ballot_sync(0xffffffffu, (__float_as_uint(w) >> 31) & 1u);
    float a = fabsf(w);
    #pragma unroll
    for (int o = 16; o; o >>= 1) a += __shfl_xor_sync(0xffffffffu, a, o);
    if (lane == 0) {
        ((unsigned*)g_wbits)[(co*9 + tap)*2 + half] = bits;  // LE: half0 = ch 0-31
        g_wasum[(co*9 + tap)*2 + half] = a;
    }
    if (blockIdx.x == 0 && threadIdx.x < Cc) {
        g_sum[threadIdx.x] = 0; g_ss[threadIdx.x] = 0;
    }
}

// ---------------- K1: fused pack + sliding-window popcount conv + BN stats -----
// 16x16 pixel tile per block. Halo stage packs 64-channel signs straight from x.
// Border corrections derived from register-resident weight bits (no tables).
__global__ __launch_bounds__(256, 2) void conv_k(const float* __restrict__ x) {
    __shared__ u64 xs[18*18];
    __shared__ int st[4][8][32];

    int tid  = threadIdx.x;
    int pair = tid & 31;
    int grp  = tid >> 5;
    int n  = blockIdx.z;
    int h0 = blockIdx.y * 16, w0 = blockIdx.x * 16;

    // fused halo pack: read 64 channel floats per halo pixel, pack sign bits
    const float* xn = x + (size_t)n*Cc*HW;
    for (int j = tid; j < 18*18; j += 256) {
        int lh = j / 18, lw = j - lh*18;
        int gh = h0 + lh - 1, gw = w0 + lw - 1;
        u64 v = 0ull;
        if (gh >= 0 && gh < Hh && gw >= 0 && gw < Wd) {
            const float* px = xn + gh*Wd + gw;
            unsigned lo = 0, hi = 0;
            #pragma unroll
            for (int c = 0; c < 32; c++)
                lo |= (__float_as_uint(__ldg(px + (size_t)c*HW)) >> 31) << c;
            #pragma unroll
            for (int c = 0; c < 32; c++)
                hi |= (__float_as_uint(__ldg(px + (size_t)(c+32)*HW)) >> 31) << c;
            v = ((u64)hi << 32) | lo;
        }
        xs[j] = v;
    }

    int c0 = pair*2;
    u64 wb0[9], wb1[9];
    #pragma unroll
    for (int t = 0; t < 9; t++) {
        wb0[t] = g_wbits[c0*9 + t];
        wb1[t] = g_wbits[(c0+1)*9 + t];
    }
    // per-tap phantom contributions (zero-padded halo): 64 - 2*popc
    int wd0[9], wd1[9];
    #pragma unroll
    for (int t = 0; t < 9; t++) {
        wd0[t] = 64 - 2*__popcll(wb0[t]);
        wd1[t] = 64 - 2*__popcll(wb1[t]);
    }
    __syncthreads();

    const bool wleft  = (w0 == 0);
    const bool wright = (w0 == Wd-16);
    int as0 = 0, ass0 = 0, as1 = 0, ass1 = 0;

    #pragma unroll
    for (int r = 0; r < 2; r++) {
        int ohl = grp*2 + r;
        int oh  = h0 + ohl;
        int rp  = (oh == 0) ? 1 : ((oh == Hh-1) ? 2 : 0);
        // row-pattern-dependent constants (uniform per warp)
        int base0, base1, cw0, cw1, ce0, ce1;
        if (rp == 1) {          // top image row: taps 0,1,2 phantom
            base0 = 576 - (wd0[0]+wd0[1]+wd0[2]);
            base1 = 576 - (wd1[0]+wd1[1]+wd1[2]);
            cw0 = wd0[3]+wd0[6];         cw1 = wd1[3]+wd1[6];
            ce0 = wd0[5]+wd0[8];         ce1 = wd1[5]+wd1[8];
        } else if (rp == 2) {   // bottom image row: taps 6,7,8 phantom
            base0 = 576 - (wd0[6]+wd0[7]+wd0[8]);
            base1 = 576 - (wd1[6]+wd1[7]+wd1[8]);
            cw0 = wd0[0]+wd0[3];         cw1 = wd1[0]+wd1[3];
            ce0 = wd0[2]+wd0[5];         ce1 = wd1[2]+wd1[5];
        } else {
            base0 = 576; base1 = 576;
            cw0 = wd0[0]+wd0[3]+wd0[6];  cw1 = wd1[0]+wd1[3]+wd1[6];
            ce0 = wd0[2]+wd0[5]+wd0[8];  ce1 = wd1[2]+wd1[5]+wd1[8];
        }

        const u64* r0p = &xs[ohl*18];
        const u64* r1p = r0p + 18;
        const u64* r2p = r1p + 18;
        u64 x00 = r0p[0], x01 = r0p[1];
        u64 x10 = r1p[0], x11 = r1p[1];
        u64 x20 = r2p[0], x21 = r2p[1];

        unsigned* op = ((unsigned*)g_conv) + ((size_t)n*HW + (size_t)oh*Wd + w0)*32 + pair;

        #pragma unroll
        for (int w = 0; w < 16; w++) {
            u64 x02 = r0p[w+2], x12 = r1p[w+2], x22 = r2p[w+2];
            int pc0 = __popcll(x00^wb0[0]) + __popcll(x01^wb0[1]) + __popcll(x02^wb0[2])
                    + __popcll(x10^wb0[3]) + __popcll(x11^wb0[4]) + __popcll(x12^wb0[5])
                    + __popcll(x20^wb0[6]) + __popcll(x21^wb0[7]) + __popcll(x22^wb0[8]);
            int pc1 = __popcll(x00^wb1[0]) + __popcll(x01^wb1[1]) + __popcll(x02^wb1[2])
                    + __popcll(x10^wb1[3]) + __popcll(x11^wb1[4]) + __popcll(x12^wb1[5])
                    + __popcll(x20^wb1[6]) + __popcll(x21^wb1[7]) + __popcll(x22^wb1[8]);
            int s0 = base0 - 2*pc0;
            int s1 = base1 - 2*pc1;
            if (w == 0  && wleft)  { s0 -= cw0; s1 -= cw1; }
            if (w == 15 && wright) { s0 -= ce0; s1 -= ce1; }

            as0 += s0; ass0 += s0*s0;
            as1 += s1; ass1 += s1*s1;
            *op = ((unsigned)s0 & 0xFFFFu) | ((unsigned)s1 << 16);
            op += 32;

            x00 = x01; x01 = x02;
            x10 = x11; x11 = x12;
            x20 = x21; x21 = x22;
        }
    }

    st[0][grp][pair] = as0; st[1][grp][pair] = ass0;
    st[2][grp][pair] = as1; st[3][grp][pair] = ass1;
    __syncthreads();
    if (grp == 0) {
        int bs0=0, bss0=0, bs1=0, bss1=0;
        #pragma unroll
        for (int g = 0; g < 8; g++) {
            bs0 += st[0][g][pair]; bss0 += st[1][g][pair];
            bs1 += st[2][g][pair]; bss1 += st[3][g][pair];
        }
        atomicAdd((unsigned long long*)&g_sum[c0],   (unsigned long long)(long long)bs0);
        atomicAdd((unsigned long long*)&g_ss[c0],    (unsigned long long)(long long)bss0);
        atomicAdd((unsigned long long*)&g_sum[c0+1], (unsigned long long)(long long)bs1);
        atomicAdd((unsigned long long*)&g_ss[c0+1],  (unsigned long long)(long long)bss1);
    }
}

// ---------------- K2: affine fold (incl. alpha) + hardtanh + residual ----------
__global__ __launch_bounds__(256) void apply_k(const float* __restrict__ x,
                                               const float* __restrict__ gamma,
                                               const float* __restrict__ beta,
                                               float* __restrict__ out) {
    __shared__ float sA[Cc], sB[Cc];
    int tid = threadIdx.x;
    if (tid < Cc) {
        int c = tid;
        float t = 0.f;
        #pragma unroll
        for (int j = 0; j < 18; j++) t += g_wasum[c*18 + j];
        double a    = (double)(t / 576.f);
        double mean = (double)g_sum[c] / (double)NHW;
        double ex2  = (double)g_ss[c]  / (double)NHW;
        double var  = a*a*(ex2 - mean*mean);
        double rs   = 1.0 / sqrt(var + BN_EPS);
        double g    = (double)gamma[c];
        sA[c] = (float)(a * rs * g);
        sB[c] = (float)((double)beta[c] - a * mean * rs * g);
    }
    __syncthreads();

    size_t P = (size_t)blockIdx.x*256 + tid;      // global pixel id
    int n = (int)(P / HW);
    int p = (int)(P - (size_t)n*HW);
    const uint4* cb = (const uint4*)g_conv + P*8;           // 128B of NHWC shorts
    const float* xb = x   + (size_t)n*Cc*HW + p;
    float*       ob = out + (size_t)n*Cc*HW + p;

    #pragma unroll
    for (int q = 0; q < 8; q++) {
        uint4 v = cb[q];
        #pragma unroll
        for (int w = 0; w < 4; w++) {
            uint32_t u = (&v.x)[w];
            int cA = (q*4 + w)*2;
            int sv0 = (int)((int32_t)(u << 16) >> 16);
            int sv1 = (int)((int32_t)u >> 16);
            float r0 = fminf(fmaxf(fmaf((float)sv0, sA[cA],   sB[cA]),   -1.f), 1.f);
            float r1 = fminf(fmaxf(fmaf((float)sv1, sA[cA+1], sB[cA+1]), -1.f), 1.f);
            ob[(size_t)cA*HW]     = r0 + xb[(size_t)cA*HW];
            ob[(size_t)(cA+1)*HW] = r1 + xb[(size_t)(cA+1)*HW];
        }
    }
}

// ---------------- launcher ------------------------------------------------------
extern "C" void kernel_launch(void* const* d_in, const int* in_sizes, int n_in,
                              void* d_out, int out_size) {
    const float* x     = (const float*)d_in[0];
    const float* W     = (const float*)d_in[1];
    const float* gamma = (const float*)d_in[2];
    const float* beta  = (const float*)d_in[3];
    float* out = (float*)d_out;

    packW_k<<<144, 256>>>(W);
    conv_k<<<dim3(7, 7, Nn), 256>>>(x);
    apply_k<<<NHW/256, 256>>>(x, gamma, beta, out);
}